// round 10
// baseline (speedup 1.0000x reference)
#include <cuda_runtime.h>
#include <cuda_fp16.h>

#define NN 50000
#define NE 600000
#define NT (NE + NN)
#define HID 128
#define NG 128
#define NC 5
#define NBLK ((NN + 255) / 256)   // 196

__device__ __forceinline__ unsigned h2_as_u(__half2 h) {
    return *reinterpret_cast<unsigned*>(&h);
}
__device__ __forceinline__ __half2 u_as_h2(unsigned u) {
    return *reinterpret_cast<__half2*>(&u);
}

// ---------------- device scratch (no allocs allowed) ----------------
__device__ int   g_cnt[NN];
__device__ float g_dis[NN];
__device__ int   g_rowptr[NN + 1];
__device__ int   g_aggflag[NBLK];               // bit30 = ready, low bits = block agg
__device__ uint2 g_ew[NT];                      // packed {col, w_bits}
__device__ __align__(16) __half g_hh[NN * HID]; // ping
__device__ __align__(16) __half g_ah[NN * HID]; // pong

// ---------------- graph normalization ----------------
__global__ void k_init() {
    int i = blockIdx.x * blockDim.x + threadIdx.x;
    if (i < NN) g_cnt[i] = 1;  // self loop
    if (i < NBLK) g_aggflag[i] = 0;
}

__global__ void k_deg(const int* __restrict__ dst) {
    int e = blockIdx.x * blockDim.x + threadIdx.x;
    if (e < NE) atomicAdd(&g_cnt[dst[e]], 1);
}

__device__ __forceinline__ int block_excl_scan_256(int v, int tid, int* wsum) {
    int lane = tid & 31, wid = tid >> 5;
    int x = v;
    #pragma unroll
    for (int o = 1; o < 32; o <<= 1) {
        int y = __shfl_up_sync(0xffffffffu, x, o);
        if (lane >= o) x += y;
    }
    if (lane == 31) wsum[wid] = x;
    __syncthreads();
    if (wid == 0) {
        int w = (lane < 8) ? wsum[lane] : 0;
        #pragma unroll
        for (int o = 1; o < 8; o <<= 1) {
            int y = __shfl_up_sync(0xffffffffu, w, o);
            if (lane >= o) w += y;
        }
        if (lane < 8) wsum[lane] = w;
    }
    __syncthreads();
    return x - v + (wid ? wsum[wid - 1] : 0);
}

// single-pass scan with lookback: dis + cnt-reset + rowptr, one kernel
__global__ void k_scan1() {
    __shared__ int wsum[8];
    __shared__ int rsum[8];
    __shared__ int s_total;
    __shared__ int s_pre;
    int tid = threadIdx.x;
    int b = blockIdx.x;
    int i = b * 256 + tid;
    int v = 0;
    if (i < NN) {
        v = g_cnt[i];
        g_dis[i] = rsqrtf((float)v);
        g_cnt[i] = 0;                 // reused as cursor by k_fill
    }
    int excl = block_excl_scan_256(v, tid, wsum);
    if (tid == 255) s_total = excl + v;
    __syncthreads();
    // publish aggregate (single word carries flag + value, no fence needed)
    if (tid == 0) atomicExch(&g_aggflag[b], 0x40000000 | s_total);
    // lookback: thread tid waits on predecessor tid (b <= 195 < 256)
    int pre = 0;
    if (tid < b) {
        int f;
        do { f = atomicAdd(&g_aggflag[tid], 0); } while (!(f & 0x40000000));
        pre = f & 0x3fffffff;
    }
    // block-reduce pre
    int lane = tid & 31, wid = tid >> 5;
    #pragma unroll
    for (int o = 16; o; o >>= 1) pre += __shfl_down_sync(0xffffffffu, pre, o);
    if (lane == 0) rsum[wid] = pre;
    __syncthreads();
    if (wid == 0) {
        int w = (lane < 8) ? rsum[lane] : 0;
        #pragma unroll
        for (int o = 4; o; o >>= 1) w += __shfl_down_sync(0xffffffffu, w, o);
        if (lane == 0) s_pre = w;
    }
    __syncthreads();
    if (i < NN) g_rowptr[i] = excl + s_pre;
    if (b == 0 && tid == 0) g_rowptr[NN] = NT;
}

__global__ void k_fill(const int* __restrict__ src, const int* __restrict__ dst) {
    int t = blockIdx.x * blockDim.x + threadIdx.x;
    if (t >= NT) return;
    int s, d;
    if (t < NE) { s = src[t]; d = dst[t]; }
    else        { s = d = t - NE; }            // self loops
    int pos = atomicAdd(&g_cnt[d], 1);
    int o = g_rowptr[d] + pos;
    uint2 v;
    v.x = (unsigned)s;
    v.y = __float_as_uint(g_dis[s] * g_dis[d]);
    g_ew[o] = v;
}

// ---------------- layer 1: h = relu((A x) W1 + b1)   (x is [N,3]) ----------------
__global__ void k_layer1(const float* __restrict__ x, const float* __restrict__ W1,
                         const float* __restrict__ b1) {
    int node = blockIdx.x * 8 + (threadIdx.x >> 5);
    if (node >= NN) return;
    int lane = threadIdx.x & 31;
    int beg = g_rowptr[node], end = g_rowptr[node + 1];
    float a0 = 0.f, a1 = 0.f, a2 = 0.f;
    for (int j = beg + lane; j < end; j += 32) {
        uint2 e = g_ew[j];
        int s = (int)e.x;
        float w = __uint_as_float(e.y);
        a0 += w * x[s * 3 + 0];
        a1 += w * x[s * 3 + 1];
        a2 += w * x[s * 3 + 2];
    }
    #pragma unroll
    for (int o = 16; o; o >>= 1) {
        a0 += __shfl_down_sync(0xffffffffu, a0, o);
        a1 += __shfl_down_sync(0xffffffffu, a1, o);
        a2 += __shfl_down_sync(0xffffffffu, a2, o);
    }
    a0 = __shfl_sync(0xffffffffu, a0, 0);
    a1 = __shfl_sync(0xffffffffu, a1, 0);
    a2 = __shfl_sync(0xffffffffu, a2, 0);
    int c = lane * 4;
    float v0 = fmaxf(a0 * W1[c+0] + a1 * W1[128+c+0] + a2 * W1[256+c+0] + b1[c+0], 0.f);
    float v1 = fmaxf(a0 * W1[c+1] + a1 * W1[128+c+1] + a2 * W1[256+c+1] + b1[c+1], 0.f);
    float v2 = fmaxf(a0 * W1[c+2] + a1 * W1[128+c+2] + a2 * W1[256+c+2] + b1[c+2], 0.f);
    float v3 = fmaxf(a0 * W1[c+3] + a1 * W1[128+c+3] + a2 * W1[256+c+3] + b1[c+3], 0.f);
    uint2 p;
    p.x = h2_as_u(__float22half2_rn(make_float2(v0, v1)));
    p.y = h2_as_u(__float22half2_rn(make_float2(v2, v3)));
    *(uint2*)(g_hh + (size_t)node * 128 + c) = p;
}

// ---------------- fused propagate + GEMM layer ----------------
// hout = relu((A hin) @ W + b); prop gathers straight into the A smem tile.
#define PA2 136   // full-width A pitch (halfs); 136/2=68 words %32 = 4 -> ldmatrix conflict-free
#define PB  136

__global__ __launch_bounds__(256) void k_pg(const __half* __restrict__ hin,
                                            __half* __restrict__ hout,
                                            const float* __restrict__ W,
                                            const float* __restrict__ bias) {
    __shared__ __align__(16) __half As[128 * PA2];  // 34.8 KB
    __shared__ __align__(16) __half Bs[32 * PB];    // 8.7 KB
    int t = threadIdx.x;
    int lane = t & 31, warp = t >> 5;
    int row0 = blockIdx.x * 128;

    // ---- phase 1: propagate 16 nodes per warp into As (fp16) ----
    for (int it = 0; it < 16; it++) {
        int r = warp * 16 + it;
        int node = row0 + r;
        float4 acc  = make_float4(0.f, 0.f, 0.f, 0.f);
        float4 acc2 = make_float4(0.f, 0.f, 0.f, 0.f);
        if (node < NN) {
            int beg = g_rowptr[node], end = g_rowptr[node + 1];
            int j = beg;
            for (; j + 3 < end; j += 4) {
                uint2 e0 = g_ew[j],     e1 = g_ew[j + 1];
                uint2 e2 = g_ew[j + 2], e3 = g_ew[j + 3];
                float w0 = __uint_as_float(e0.y), w1 = __uint_as_float(e1.y);
                float w2 = __uint_as_float(e2.y), w3 = __uint_as_float(e3.y);
                uint2 h0 = *(const uint2*)(hin + (size_t)e0.x * 128 + lane * 4);
                uint2 h1 = *(const uint2*)(hin + (size_t)e1.x * 128 + lane * 4);
                uint2 h2 = *(const uint2*)(hin + (size_t)e2.x * 128 + lane * 4);
                uint2 h3 = *(const uint2*)(hin + (size_t)e3.x * 128 + lane * 4);
                float2 p0 = __half22float2(u_as_h2(h0.x)), p1 = __half22float2(u_as_h2(h0.y));
                float2 q0 = __half22float2(u_as_h2(h1.x)), q1 = __half22float2(u_as_h2(h1.y));
                float2 r0 = __half22float2(u_as_h2(h2.x)), r1 = __half22float2(u_as_h2(h2.y));
                float2 s0 = __half22float2(u_as_h2(h3.x)), s1 = __half22float2(u_as_h2(h3.y));
                acc.x  += w0 * p0.x; acc.y  += w0 * p0.y; acc.z  += w0 * p1.x; acc.w  += w0 * p1.y;
                acc2.x += w1 * q0.x; acc2.y += w1 * q0.y; acc2.z += w1 * q1.x; acc2.w += w1 * q1.y;
                acc.x  += w2 * r0.x; acc.y  += w2 * r0.y; acc.z  += w2 * r1.x; acc.w  += w2 * r1.y;
                acc2.x += w3 * s0.x; acc2.y += w3 * s0.y; acc2.z += w3 * s1.x; acc2.w += w3 * s1.y;
            }
            for (; j < end; j++) {
                uint2 e = g_ew[j];
                float w = __uint_as_float(e.y);
                uint2 h = *(const uint2*)(hin + (size_t)e.x * 128 + lane * 4);
                float2 p0 = __half22float2(u_as_h2(h.x));
                float2 p1 = __half22float2(u_as_h2(h.y));
                acc.x += w * p0.x; acc.y += w * p0.y; acc.z += w * p1.x; acc.w += w * p1.y;
            }
        }
        acc.x += acc2.x; acc.y += acc2.y; acc.z += acc2.z; acc.w += acc2.w;
        uint2 o;
        o.x = h2_as_u(__float22half2_rn(make_float2(acc.x, acc.y)));
        o.y = h2_as_u(__float22half2_rn(make_float2(acc.z, acc.w)));
        *(uint2*)(As + r * PA2 + lane * 4) = o;
    }
    __syncthreads();

    // ---- phase 2: GEMM from smem ----
    int wm = warp & 3, wn = warp >> 2;             // 4 (m) x 2 (n) warps
    int lm = lane >> 3, lr = lane & 7;

    float acc[2][8][4];
    #pragma unroll
    for (int mt = 0; mt < 2; mt++)
        #pragma unroll
        for (int nt = 0; nt < 8; nt++)
            #pragma unroll
            for (int d = 0; d < 4; d++) acc[mt][nt][d] = 0.f;

    for (int k0 = 0; k0 < 128; k0 += 32) {
        // B chunk: 32 rows x 128 cols, fp32 -> fp16
        #pragma unroll
        for (int i = 0; i < 4; i++) {
            int lin = t + i * 256;                 // 0..1023
            int kk = lin >> 5, c4 = (lin & 31) * 4;
            float4 wv = *(const float4*)(W + (size_t)(k0 + kk) * 128 + c4);
            uint2 p;
            p.x = h2_as_u(__float22half2_rn(make_float2(wv.x, wv.y)));
            p.y = h2_as_u(__float22half2_rn(make_float2(wv.z, wv.w)));
            *(uint2*)(Bs + kk * PB + c4) = p;
        }
        __syncthreads();

        #pragma unroll
        for (int kk = 0; kk < 32; kk += 16) {
            unsigned a[2][4];
            #pragma unroll
            for (int mt = 0; mt < 2; mt++) {
                const __half* ap = As + (wm * 32 + mt * 16 + (lm & 1) * 8 + lr) * PA2
                                      + k0 + kk + (lm >> 1) * 8;
                unsigned addr = (unsigned)__cvta_generic_to_shared(ap);
                asm volatile("ldmatrix.sync.aligned.m8n8.x4.shared.b16 {%0,%1,%2,%3}, [%4];"
                             : "=r"(a[mt][0]), "=r"(a[mt][1]), "=r"(a[mt][2]), "=r"(a[mt][3])
                             : "r"(addr));
            }
            unsigned b[8][2];
            #pragma unroll
            for (int nt16 = 0; nt16 < 4; nt16++) {
                const __half* bp = Bs + (kk + (lm & 1) * 8 + lr) * PB
                                      + wn * 64 + nt16 * 16 + (lm >> 1) * 8;
                unsigned addr = (unsigned)__cvta_generic_to_shared(bp);
                asm volatile("ldmatrix.sync.aligned.m8n8.x4.trans.shared.b16 {%0,%1,%2,%3}, [%4];"
                             : "=r"(b[2*nt16][0]), "=r"(b[2*nt16][1]),
                               "=r"(b[2*nt16+1][0]), "=r"(b[2*nt16+1][1])
                             : "r"(addr));
            }
            #pragma unroll
            for (int mt = 0; mt < 2; mt++)
                #pragma unroll
                for (int nt = 0; nt < 8; nt++) {
                    asm volatile(
                        "mma.sync.aligned.m16n8k16.row.col.f32.f16.f16.f32 "
                        "{%0,%1,%2,%3}, {%4,%5,%6,%7}, {%8,%9}, {%0,%1,%2,%3};"
                        : "+f"(acc[mt][nt][0]), "+f"(acc[mt][nt][1]),
                          "+f"(acc[mt][nt][2]), "+f"(acc[mt][nt][3])
                        : "r"(a[mt][0]), "r"(a[mt][1]), "r"(a[mt][2]), "r"(a[mt][3]),
                          "r"(b[nt][0]), "r"(b[nt][1]));
                }
        }
        __syncthreads();
    }

    // ---- epilogue: bias + relu -> fp16 hout ----
    #pragma unroll
    for (int nt = 0; nt < 8; nt++) {
        int col = wn * 64 + nt * 8 + (lane & 3) * 2;
        float2 bv = *(const float2*)(bias + col);
        #pragma unroll
        for (int mt = 0; mt < 2; mt++) {
            int rA = row0 + wm * 32 + mt * 16 + (lane >> 2);
            if (rA < NN) {
                float2 v = make_float2(fmaxf(acc[mt][nt][0] + bv.x, 0.f),
                                       fmaxf(acc[mt][nt][1] + bv.y, 0.f));
                *(__half2*)(hout + (size_t)rA * 128 + col) = __float22half2_rn(v);
            }
            int rB = rA + 8;
            if (rB < NN) {
                float2 v = make_float2(fmaxf(acc[mt][nt][2] + bv.x, 0.f),
                                       fmaxf(acc[mt][nt][3] + bv.y, 0.f));
                *(__half2*)(hout + (size_t)rB * 128 + col) = __float22half2_rn(v);
            }
        }
    }
}

// ---------------- fused mean-pool + classifier head ----------------
__global__ void k_poolfinal(const int* __restrict__ batch, const float* __restrict__ Wl,
                            const float* __restrict__ bl, float* __restrict__ out) {
    __shared__ float spool[128];
    int g = blockIdx.x;   // 0..127
    int c = threadIdx.x;  // 0..127
    int lo = 0, hi = NN;
    while (lo < hi) { int m = (lo + hi) >> 1; if (batch[m] < g) lo = m + 1; else hi = m; }
    int st = lo;
    lo = st; hi = NN;
    while (lo < hi) { int m = (lo + hi) >> 1; if (batch[m] < g + 1) lo = m + 1; else hi = m; }
    int en = lo;
    float s0 = 0.f, s1 = 0.f, s2 = 0.f, s3 = 0.f;
    int n = st;
    for (; n + 3 < en; n += 4) {
        s0 += __half2float(g_hh[(size_t)(n + 0) * 128 + c]);
        s1 += __half2float(g_hh[(size_t)(n + 1) * 128 + c]);
        s2 += __half2float(g_hh[(size_t)(n + 2) * 128 + c]);
        s3 += __half2float(g_hh[(size_t)(n + 3) * 128 + c]);
    }
    for (; n < en; n++) s0 += __half2float(g_hh[(size_t)n * 128 + c]);
    float s = (s0 + s1) + (s2 + s3);
    int cnt = en - st;
    spool[c] = s / (float)(cnt > 0 ? cnt : 1);
    __syncthreads();

    int lane = c & 31, warp = c >> 5;              // 4 warps
    for (int j = warp; j < NC; j += 4) {
        float p = 0.f;
        #pragma unroll
        for (int i = 0; i < 4; i++) {
            int k = lane + 32 * i;
            p += spool[k] * Wl[k * NC + j];
        }
        #pragma unroll
        for (int o = 16; o; o >>= 1) p += __shfl_down_sync(0xffffffffu, p, o);
        if (lane == 0) out[g * NC + j] = p + bl[j];
    }
}

extern "C" void kernel_launch(void* const* d_in, const int* in_sizes, int n_in,
                              void* d_out, int out_size) {
    const float* x     = (const float*)d_in[0];
    const int*   ei    = (const int*)d_in[1];
    const int*   batch = (const int*)d_in[2];
    const float* W1    = (const float*)d_in[3];
    const float* b1    = (const float*)d_in[4];
    const float* W2    = (const float*)d_in[5];
    const float* b2    = (const float*)d_in[6];
    const float* W3    = (const float*)d_in[7];
    const float* b3    = (const float*)d_in[8];
    const float* Wl    = (const float*)d_in[9];
    const float* bl    = (const float*)d_in[10];
    float* out = (float*)d_out;

    const int* src = ei;          // edge_index[0]
    const int* dst = ei + NE;     // edge_index[1]

    // allow 2 blocks/SM worth of shared memory for the fused kernel
    cudaFuncSetAttribute(k_pg, cudaFuncAttributePreferredSharedMemoryCarveout, 100);

    // graph norm + CSR build (single-pass lookback scan)
    k_init <<<(NN + 255) / 256, 256>>>();
    k_deg  <<<(NE + 255) / 256, 256>>>(dst);
    k_scan1<<<NBLK, 256>>>();
    k_fill <<<(NT + 255) / 256, 256>>>(src, dst);

    // layer 1 (fused propagate-3dim + tiny GEMM + bias + relu) -> g_hh
    k_layer1<<<(NN + 7) / 8, 256>>>(x, W1, b1);

    // layers 2 & 3: fused propagate + HMMA GEMM, ping-pong buffers
    __half *hh_p = nullptr, *ah_p = nullptr;
    cudaGetSymbolAddress((void**)&hh_p, g_hh);
    cudaGetSymbolAddress((void**)&ah_p, g_ah);
    k_pg<<<(NN + 127) / 128, 256>>>(hh_p, ah_p, W2, b2);
    k_pg<<<(NN + 127) / 128, 256>>>(ah_p, hh_p, W3, b3);

    // pool + classifier head (fused)
    k_poolfinal<<<NG, HID>>>(batch, Wl, bl, out);
}

// round 11
// speedup vs baseline: 1.6095x; 1.6095x over previous
#include <cuda_runtime.h>
#include <cuda_fp16.h>

#define NN 50000
#define NE 600000
#define NT (NE + NN)
#define HID 128
#define NG 128
#define NC 5
#define NBLK ((NN + 255) / 256)   // 196

__device__ __forceinline__ unsigned h2_as_u(__half2 h) {
    return *reinterpret_cast<unsigned*>(&h);
}
__device__ __forceinline__ __half2 u_as_h2(unsigned u) {
    return *reinterpret_cast<__half2*>(&u);
}

// ---------------- device scratch (no allocs allowed) ----------------
__device__ int   g_cnt[NN];
__device__ float g_dis[NN];
__device__ int   g_rowptr[NN + 1];
__device__ int   g_aggflag[NBLK];               // bit30 = ready, low bits = block agg
__device__ uint2 g_ew[NT];                      // packed {col, w_bits}
__device__ __align__(16) __half g_hh[NN * HID]; // activations (fp16)
__device__ __align__(16) __half g_ah[NN * HID]; // aggregated (fp16)

// ---------------- graph normalization ----------------
__global__ void k_init() {
    int i = blockIdx.x * blockDim.x + threadIdx.x;
    if (i < NN) g_cnt[i] = 1;  // self loop
    if (i < NBLK) g_aggflag[i] = 0;
}

__global__ void k_deg(const int* __restrict__ dst) {
    int e = blockIdx.x * blockDim.x + threadIdx.x;
    if (e < NE) atomicAdd(&g_cnt[dst[e]], 1);
}

__device__ __forceinline__ int block_excl_scan_256(int v, int tid, int* wsum) {
    int lane = tid & 31, wid = tid >> 5;
    int x = v;
    #pragma unroll
    for (int o = 1; o < 32; o <<= 1) {
        int y = __shfl_up_sync(0xffffffffu, x, o);
        if (lane >= o) x += y;
    }
    if (lane == 31) wsum[wid] = x;
    __syncthreads();
    if (wid == 0) {
        int w = (lane < 8) ? wsum[lane] : 0;
        #pragma unroll
        for (int o = 1; o < 8; o <<= 1) {
            int y = __shfl_up_sync(0xffffffffu, w, o);
            if (lane >= o) w += y;
        }
        if (lane < 8) wsum[lane] = w;
    }
    __syncthreads();
    return x - v + (wid ? wsum[wid - 1] : 0);
}

// single-pass scan with lookback: dis + cnt-reset + rowptr, one kernel
__global__ void k_scan1() {
    __shared__ int wsum[8];
    __shared__ int rsum[8];
    __shared__ int s_total;
    __shared__ int s_pre;
    int tid = threadIdx.x;
    int b = blockIdx.x;
    int i = b * 256 + tid;
    int v = 0;
    if (i < NN) {
        v = g_cnt[i];
        g_dis[i] = rsqrtf((float)v);
        g_cnt[i] = 0;                 // reused as cursor by k_fill
    }
    int excl = block_excl_scan_256(v, tid, wsum);
    if (tid == 255) s_total = excl + v;
    __syncthreads();
    // publish aggregate (single word carries flag + value)
    if (tid == 0) atomicExch(&g_aggflag[b], 0x40000000 | s_total);
    // lookback: thread tid waits on predecessor tid (b <= 195 < 256)
    int pre = 0;
    if (tid < b) {
        int f;
        do { f = atomicAdd(&g_aggflag[tid], 0); } while (!(f & 0x40000000));
        pre = f & 0x3fffffff;
    }
    int lane = tid & 31, wid = tid >> 5;
    #pragma unroll
    for (int o = 16; o; o >>= 1) pre += __shfl_down_sync(0xffffffffu, pre, o);
    if (lane == 0) rsum[wid] = pre;
    __syncthreads();
    if (wid == 0) {
        int w = (lane < 8) ? rsum[lane] : 0;
        #pragma unroll
        for (int o = 4; o; o >>= 1) w += __shfl_down_sync(0xffffffffu, w, o);
        if (lane == 0) s_pre = w;
    }
    __syncthreads();
    if (i < NN) g_rowptr[i] = excl + s_pre;
    if (b == 0 && tid == 0) g_rowptr[NN] = NT;
}

__global__ void k_fill(const int* __restrict__ src, const int* __restrict__ dst) {
    int t = blockIdx.x * blockDim.x + threadIdx.x;
    if (t >= NT) return;
    int s, d;
    if (t < NE) { s = src[t]; d = dst[t]; }
    else        { s = d = t - NE; }            // self loops
    int pos = atomicAdd(&g_cnt[d], 1);
    int o = g_rowptr[d] + pos;
    uint2 v;
    v.x = (unsigned)s;
    v.y = __float_as_uint(g_dis[s] * g_dis[d]);
    g_ew[o] = v;
}

// ---------------- layer 1: h = relu((A x) W1 + b1)   (x is [N,3]) ----------------
__global__ void k_layer1(const float* __restrict__ x, const float* __restrict__ W1,
                         const float* __restrict__ b1) {
    int node = blockIdx.x * 8 + (threadIdx.x >> 5);
    if (node >= NN) return;
    int lane = threadIdx.x & 31;
    int beg = g_rowptr[node], end = g_rowptr[node + 1];
    float a0 = 0.f, a1 = 0.f, a2 = 0.f;
    for (int j = beg + lane; j < end; j += 32) {
        uint2 e = g_ew[j];
        int s = (int)e.x;
        float w = __uint_as_float(e.y);
        a0 += w * x[s * 3 + 0];
        a1 += w * x[s * 3 + 1];
        a2 += w * x[s * 3 + 2];
    }
    #pragma unroll
    for (int o = 16; o; o >>= 1) {
        a0 += __shfl_down_sync(0xffffffffu, a0, o);
        a1 += __shfl_down_sync(0xffffffffu, a1, o);
        a2 += __shfl_down_sync(0xffffffffu, a2, o);
    }
    a0 = __shfl_sync(0xffffffffu, a0, 0);
    a1 = __shfl_sync(0xffffffffu, a1, 0);
    a2 = __shfl_sync(0xffffffffu, a2, 0);
    int c = lane * 4;
    float v0 = fmaxf(a0 * W1[c+0] + a1 * W1[128+c+0] + a2 * W1[256+c+0] + b1[c+0], 0.f);
    float v1 = fmaxf(a0 * W1[c+1] + a1 * W1[128+c+1] + a2 * W1[256+c+1] + b1[c+1], 0.f);
    float v2 = fmaxf(a0 * W1[c+2] + a1 * W1[128+c+2] + a2 * W1[256+c+2] + b1[c+2], 0.f);
    float v3 = fmaxf(a0 * W1[c+3] + a1 * W1[128+c+3] + a2 * W1[256+c+3] + b1[c+3], 0.f);
    uint2 p;
    p.x = h2_as_u(__float22half2_rn(make_float2(v0, v1)));
    p.y = h2_as_u(__float22half2_rn(make_float2(v2, v3)));
    *(uint2*)(g_hh + (size_t)node * 128 + c) = p;
}

// ---------------- propagate: g_ah = A * g_hh  (warp/node, lane = 4 ch, fp16) ----------------
__global__ void k_prop() {
    int node = blockIdx.x * 8 + (threadIdx.x >> 5);
    if (node >= NN) return;
    int lane = threadIdx.x & 31;
    int beg = g_rowptr[node], end = g_rowptr[node + 1];
    float4 acc  = make_float4(0.f, 0.f, 0.f, 0.f);
    float4 acc2 = make_float4(0.f, 0.f, 0.f, 0.f);
    int j = beg;
    for (; j + 3 < end; j += 4) {
        uint2 e0 = g_ew[j],     e1 = g_ew[j + 1];
        uint2 e2 = g_ew[j + 2], e3 = g_ew[j + 3];
        float w0 = __uint_as_float(e0.y), w1 = __uint_as_float(e1.y);
        float w2 = __uint_as_float(e2.y), w3 = __uint_as_float(e3.y);
        uint2 h0 = *(const uint2*)(g_hh + (size_t)e0.x * 128 + lane * 4);
        uint2 h1 = *(const uint2*)(g_hh + (size_t)e1.x * 128 + lane * 4);
        uint2 h2 = *(const uint2*)(g_hh + (size_t)e2.x * 128 + lane * 4);
        uint2 h3 = *(const uint2*)(g_hh + (size_t)e3.x * 128 + lane * 4);
        float2 p0 = __half22float2(u_as_h2(h0.x)), p1 = __half22float2(u_as_h2(h0.y));
        float2 q0 = __half22float2(u_as_h2(h1.x)), q1 = __half22float2(u_as_h2(h1.y));
        float2 r0 = __half22float2(u_as_h2(h2.x)), r1 = __half22float2(u_as_h2(h2.y));
        float2 s0 = __half22float2(u_as_h2(h3.x)), s1 = __half22float2(u_as_h2(h3.y));
        acc.x  += w0 * p0.x; acc.y  += w0 * p0.y; acc.z  += w0 * p1.x; acc.w  += w0 * p1.y;
        acc2.x += w1 * q0.x; acc2.y += w1 * q0.y; acc2.z += w1 * q1.x; acc2.w += w1 * q1.y;
        acc.x  += w2 * r0.x; acc.y  += w2 * r0.y; acc.z  += w2 * r1.x; acc.w  += w2 * r1.y;
        acc2.x += w3 * s0.x; acc2.y += w3 * s0.y; acc2.z += w3 * s1.x; acc2.w += w3 * s1.y;
    }
    for (; j < end; j++) {
        uint2 e = g_ew[j];
        float w = __uint_as_float(e.y);
        uint2 h = *(const uint2*)(g_hh + (size_t)e.x * 128 + lane * 4);
        float2 p0 = __half22float2(u_as_h2(h.x));
        float2 p1 = __half22float2(u_as_h2(h.y));
        acc.x += w * p0.x; acc.y += w * p0.y; acc.z += w * p1.x; acc.w += w * p1.y;
    }
    acc.x += acc2.x; acc.y += acc2.y; acc.z += acc2.z; acc.w += acc2.w;
    uint2 o;
    o.x = h2_as_u(__float22half2_rn(make_float2(acc.x, acc.y)));
    o.y = h2_as_u(__float22half2_rn(make_float2(acc.z, acc.w)));
    *(uint2*)(g_ah + (size_t)node * 128 + lane * 4) = o;
}

// ---------------- GEMM (HMMA): g_hh = relu(g_ah @ W + b), [N,128]x[128,128] ----------------
#define PA 72    // A smem pitch (halfs): 144B -> ldmatrix rows hit distinct 16B groups
#define PB 136   // B smem pitch (halfs): 272B -> same

__global__ __launch_bounds__(256, 2) void k_gemm(const float* __restrict__ W,
                                                 const float* __restrict__ bias) {
    __shared__ __align__(16) __half As[128 * PA];  // 18KB
    __shared__ __align__(16) __half Bs[64 * PB];   // 17KB
    int t = threadIdx.x;
    int lane = t & 31, warp = t >> 5;
    int wm = warp & 3, wn = warp >> 2;             // 4 (m) x 2 (n) warps
    int row0 = blockIdx.x * 128;

    float acc[2][8][4];
    #pragma unroll
    for (int mt = 0; mt < 2; mt++)
        #pragma unroll
        for (int nt = 0; nt < 8; nt++)
            #pragma unroll
            for (int d = 0; d < 4; d++) acc[mt][nt][d] = 0.f;

    int lm = lane >> 3, lr = lane & 7;             // ldmatrix addressing helpers

    for (int k0 = 0; k0 < 128; k0 += 64) {
        // A tile: 128 rows x 64 halfs, from g_ah
        #pragma unroll
        for (int i = 0; i < 4; i++) {
            int lin = t + i * 256;                 // 0..1023
            int r = lin >> 3, c8 = (lin & 7) * 8;
            uint4 v = make_uint4(0u, 0u, 0u, 0u);
            if (row0 + r < NN)
                v = *(const uint4*)(g_ah + (size_t)(row0 + r) * 128 + k0 + c8);
            *(uint4*)(As + r * PA + c8) = v;
        }
        // B tile: 64 rows x 128 cols, from fp32 W, convert to fp16
        #pragma unroll
        for (int i = 0; i < 8; i++) {
            int lin = t + i * 256;                 // 0..2047
            int kk = lin >> 5, c4 = (lin & 31) * 4;
            float4 wv = *(const float4*)(W + (size_t)(k0 + kk) * 128 + c4);
            uint2 p;
            p.x = h2_as_u(__float22half2_rn(make_float2(wv.x, wv.y)));
            p.y = h2_as_u(__float22half2_rn(make_float2(wv.z, wv.w)));
            *(uint2*)(Bs + kk * PB + c4) = p;
        }
        __syncthreads();

        #pragma unroll
        for (int kk = 0; kk < 64; kk += 16) {
            unsigned a[2][4];
            #pragma unroll
            for (int mt = 0; mt < 2; mt++) {
                const __half* ap = As + (wm * 32 + mt * 16 + (lm & 1) * 8 + lr) * PA
                                      + kk + (lm >> 1) * 8;
                unsigned addr = (unsigned)__cvta_generic_to_shared(ap);
                asm volatile("ldmatrix.sync.aligned.m8n8.x4.shared.b16 {%0,%1,%2,%3}, [%4];"
                             : "=r"(a[mt][0]), "=r"(a[mt][1]), "=r"(a[mt][2]), "=r"(a[mt][3])
                             : "r"(addr));
            }
            unsigned b[8][2];
            #pragma unroll
            for (int nt16 = 0; nt16 < 4; nt16++) {
                const __half* bp = Bs + (kk + (lm & 1) * 8 + lr) * PB
                                      + wn * 64 + nt16 * 16 + (lm >> 1) * 8;
                unsigned addr = (unsigned)__cvta_generic_to_shared(bp);
                asm volatile("ldmatrix.sync.aligned.m8n8.x4.trans.shared.b16 {%0,%1,%2,%3}, [%4];"
                             : "=r"(b[2*nt16][0]), "=r"(b[2*nt16][1]),
                               "=r"(b[2*nt16+1][0]), "=r"(b[2*nt16+1][1])
                             : "r"(addr));
            }
            #pragma unroll
            for (int mt = 0; mt < 2; mt++)
                #pragma unroll
                for (int nt = 0; nt < 8; nt++) {
                    asm volatile(
                        "mma.sync.aligned.m16n8k16.row.col.f32.f16.f16.f32 "
                        "{%0,%1,%2,%3}, {%4,%5,%6,%7}, {%8,%9}, {%0,%1,%2,%3};"
                        : "+f"(acc[mt][nt][0]), "+f"(acc[mt][nt][1]),
                          "+f"(acc[mt][nt][2]), "+f"(acc[mt][nt][3])
                        : "r"(a[mt][0]), "r"(a[mt][1]), "r"(a[mt][2]), "r"(a[mt][3]),
                          "r"(b[nt][0]), "r"(b[nt][1]));
                }
        }
        __syncthreads();
    }

    // epilogue: bias + relu -> fp16 h
    #pragma unroll
    for (int nt = 0; nt < 8; nt++) {
        int col = wn * 64 + nt * 8 + (lane & 3) * 2;
        float2 bv = *(const float2*)(bias + col);
        #pragma unroll
        for (int mt = 0; mt < 2; mt++) {
            int rA = row0 + wm * 32 + mt * 16 + (lane >> 2);
            if (rA < NN) {
                float2 v = make_float2(fmaxf(acc[mt][nt][0] + bv.x, 0.f),
                                       fmaxf(acc[mt][nt][1] + bv.y, 0.f));
                *(__half2*)(g_hh + (size_t)rA * 128 + col) = __float22half2_rn(v);
            }
            int rB = rA + 8;
            if (rB < NN) {
                float2 v = make_float2(fmaxf(acc[mt][nt][2] + bv.x, 0.f),
                                       fmaxf(acc[mt][nt][3] + bv.y, 0.f));
                *(__half2*)(g_hh + (size_t)rB * 128 + col) = __float22half2_rn(v);
            }
        }
    }
}

// ---------------- fused mean-pool + classifier head ----------------
__global__ void k_poolfinal(const int* __restrict__ batch, const float* __restrict__ Wl,
                            const float* __restrict__ bl, float* __restrict__ out) {
    __shared__ float spool[128];
    int g = blockIdx.x;   // 0..127
    int c = threadIdx.x;  // 0..127
    int lo = 0, hi = NN;
    while (lo < hi) { int m = (lo + hi) >> 1; if (batch[m] < g) lo = m + 1; else hi = m; }
    int st = lo;
    lo = st; hi = NN;
    while (lo < hi) { int m = (lo + hi) >> 1; if (batch[m] < g + 1) lo = m + 1; else hi = m; }
    int en = lo;
    float s0 = 0.f, s1 = 0.f, s2 = 0.f, s3 = 0.f;
    int n = st;
    for (; n + 3 < en; n += 4) {
        s0 += __half2float(g_hh[(size_t)(n + 0) * 128 + c]);
        s1 += __half2float(g_hh[(size_t)(n + 1) * 128 + c]);
        s2 += __half2float(g_hh[(size_t)(n + 2) * 128 + c]);
        s3 += __half2float(g_hh[(size_t)(n + 3) * 128 + c]);
    }
    for (; n < en; n++) s0 += __half2float(g_hh[(size_t)n * 128 + c]);
    float s = (s0 + s1) + (s2 + s3);
    int cnt = en - st;
    spool[c] = s / (float)(cnt > 0 ? cnt : 1);
    __syncthreads();

    int lane = c & 31, warp = c >> 5;              // 4 warps
    for (int j = warp; j < NC; j += 4) {
        float p = 0.f;
        #pragma unroll
        for (int i = 0; i < 4; i++) {
            int k = lane + 32 * i;
            p += spool[k] * Wl[k * NC + j];
        }
        #pragma unroll
        for (int o = 16; o; o >>= 1) p += __shfl_down_sync(0xffffffffu, p, o);
        if (lane == 0) out[g * NC + j] = p + bl[j];
    }
}

extern "C" void kernel_launch(void* const* d_in, const int* in_sizes, int n_in,
                              void* d_out, int out_size) {
    const float* x     = (const float*)d_in[0];
    const int*   ei    = (const int*)d_in[1];
    const int*   batch = (const int*)d_in[2];
    const float* W1    = (const float*)d_in[3];
    const float* b1    = (const float*)d_in[4];
    const float* W2    = (const float*)d_in[5];
    const float* b2    = (const float*)d_in[6];
    const float* W3    = (const float*)d_in[7];
    const float* b3    = (const float*)d_in[8];
    const float* Wl    = (const float*)d_in[9];
    const float* bl    = (const float*)d_in[10];
    float* out = (float*)d_out;

    const int* src = ei;          // edge_index[0]
    const int* dst = ei + NE;     // edge_index[1]

    // graph norm + CSR build (single-pass lookback scan)
    k_init <<<(NN + 255) / 256, 256>>>();
    k_deg  <<<(NE + 255) / 256, 256>>>(dst);
    k_scan1<<<NBLK, 256>>>();
    k_fill <<<(NT + 255) / 256, 256>>>(src, dst);

    // layer 1 (fused propagate-3dim + tiny GEMM + bias + relu) -> g_hh
    k_layer1<<<(NN + 7) / 8, 256>>>(x, W1, b1);

    // layer 2
    k_prop<<<(NN + 7) / 8, 256>>>();
    k_gemm<<<(NN + 127) / 128, 256>>>(W2, b2);

    // layer 3
    k_prop<<<(NN + 7) / 8, 256>>>();
    k_gemm<<<(NN + 127) / 128, 256>>>(W3, b3);

    // pool + classifier head (fused)
    k_poolfinal<<<NG, HID>>>(batch, Wl, bl, out);
}

// round 14
// speedup vs baseline: 1.6917x; 1.0511x over previous
#include <cuda_runtime.h>
#include <cuda_fp16.h>

#define NN 50000
#define NE 600000
#define NT (NE + NN)
#define HID 128
#define NG 128
#define NC 5
#define NBLK ((NN + 255) / 256)   // 196

__device__ __forceinline__ unsigned h2_as_u(__half2 h) {
    return *reinterpret_cast<unsigned*>(&h);
}
__device__ __forceinline__ __half2 u_as_h2(unsigned u) {
    return *reinterpret_cast<__half2*>(&u);
}

// ---------------- device scratch (no allocs allowed) ----------------
__device__ int    g_cnt[NN];
__device__ float  g_dis[NN];
__device__ int    g_rowptr[NN + 1];
__device__ int    g_aggflag[NBLK];               // bit30 = ready, low bits = block agg
__device__ int    g_col[NT];                     // CSR columns only (norm folded into nodes)
__device__ __align__(16) float4 g_xs4[NN];       // dis[n] * x[n], padded to float4
__device__ __align__(16) __half g_hh[NN * HID];  // activations (fp16)
__device__ __align__(16) __half g_ah[NN * HID];  // aggregated (fp16)

// ---------------- graph normalization ----------------
__global__ void k_init() {
    int i = blockIdx.x * blockDim.x + threadIdx.x;
    if (i < NN) g_cnt[i] = 1;  // self loop
    if (i < NBLK) g_aggflag[i] = 0;
}

__global__ void k_deg(const int* __restrict__ dst) {
    int e = blockIdx.x * blockDim.x + threadIdx.x;
    if (e < NE) atomicAdd(&g_cnt[dst[e]], 1);
}

__device__ __forceinline__ int block_excl_scan_256(int v, int tid, int* wsum) {
    int lane = tid & 31, wid = tid >> 5;
    int x = v;
    #pragma unroll
    for (int o = 1; o < 32; o <<= 1) {
        int y = __shfl_up_sync(0xffffffffu, x, o);
        if (lane >= o) x += y;
    }
    if (lane == 31) wsum[wid] = x;
    __syncthreads();
    if (wid == 0) {
        int w = (lane < 8) ? wsum[lane] : 0;
        #pragma unroll
        for (int o = 1; o < 8; o <<= 1) {
            int y = __shfl_up_sync(0xffffffffu, w, o);
            if (lane >= o) w += y;
        }
        if (lane < 8) wsum[lane] = w;
    }
    __syncthreads();
    return x - v + (wid ? wsum[wid - 1] : 0);
}

// single-pass scan with lookback; also computes dis and xs4 = dis*x, resets cnt
__global__ void k_scan1(const float* __restrict__ x) {
    __shared__ int wsum[8];
    __shared__ int rsum[8];
    __shared__ int s_total;
    __shared__ int s_pre;
    int tid = threadIdx.x;
    int b = blockIdx.x;
    int i = b * 256 + tid;
    int v = 0;
    if (i < NN) {
        v = g_cnt[i];
        float dis = rsqrtf((float)v);
        g_dis[i] = dis;
        g_xs4[i] = make_float4(dis * x[i * 3 + 0], dis * x[i * 3 + 1],
                               dis * x[i * 3 + 2], 0.f);
        g_cnt[i] = 0;                 // reused as cursor by k_fill
    }
    int excl = block_excl_scan_256(v, tid, wsum);
    if (tid == 255) s_total = excl + v;
    __syncthreads();
    if (tid == 0) atomicExch(&g_aggflag[b], 0x40000000 | s_total);
    int pre = 0;
    if (tid < b) {
        int f;
        do { f = atomicAdd(&g_aggflag[tid], 0); } while (!(f & 0x40000000));
        pre = f & 0x3fffffff;
    }
    int lane = tid & 31, wid = tid >> 5;
    #pragma unroll
    for (int o = 16; o; o >>= 1) pre += __shfl_down_sync(0xffffffffu, pre, o);
    if (lane == 0) rsum[wid] = pre;
    __syncthreads();
    if (wid == 0) {
        int w = (lane < 8) ? rsum[lane] : 0;
        #pragma unroll
        for (int o = 4; o; o >>= 1) w += __shfl_down_sync(0xffffffffu, w, o);
        if (lane == 0) s_pre = w;
    }
    __syncthreads();
    if (i < NN) g_rowptr[i] = excl + s_pre;
    if (b == 0 && tid == 0) g_rowptr[NN] = NT;
}

__global__ void k_fill(const int* __restrict__ src, const int* __restrict__ dst) {
    int t = blockIdx.x * blockDim.x + threadIdx.x;
    if (t >= NT) return;
    int s, d;
    if (t < NE) { s = src[t]; d = dst[t]; }
    else        { s = d = t - NE; }            // self loops
    int pos = atomicAdd(&g_cnt[d], 1);
    g_col[g_rowptr[d] + pos] = s;
}

// ---------------- layer 1: h1' = dis * relu( dis*(sum xs4) @ W1 + b1 ) ----------------
__global__ void k_layer1(const float* __restrict__ W1, const float* __restrict__ b1) {
    int node = blockIdx.x * 8 + (threadIdx.x >> 5);
    if (node >= NN) return;
    int lane = threadIdx.x & 31;
    int beg = g_rowptr[node], end = g_rowptr[node + 1];
    float a0 = 0.f, a1 = 0.f, a2 = 0.f;
    for (int j = beg + lane; j < end; j += 32) {
        float4 v = g_xs4[g_col[j]];
        a0 += v.x; a1 += v.y; a2 += v.z;
    }
    #pragma unroll
    for (int o = 16; o; o >>= 1) {
        a0 += __shfl_down_sync(0xffffffffu, a0, o);
        a1 += __shfl_down_sync(0xffffffffu, a1, o);
        a2 += __shfl_down_sync(0xffffffffu, a2, o);
    }
    float dis = g_dis[node];
    a0 = __shfl_sync(0xffffffffu, a0, 0) * dis;
    a1 = __shfl_sync(0xffffffffu, a1, 0) * dis;
    a2 = __shfl_sync(0xffffffffu, a2, 0) * dis;
    int c = lane * 4;
    float v0 = dis * fmaxf(a0 * W1[c+0] + a1 * W1[128+c+0] + a2 * W1[256+c+0] + b1[c+0], 0.f);
    float v1 = dis * fmaxf(a0 * W1[c+1] + a1 * W1[128+c+1] + a2 * W1[256+c+1] + b1[c+1], 0.f);
    float v2 = dis * fmaxf(a0 * W1[c+2] + a1 * W1[128+c+2] + a2 * W1[256+c+2] + b1[c+2], 0.f);
    float v3 = dis * fmaxf(a0 * W1[c+3] + a1 * W1[128+c+3] + a2 * W1[256+c+3] + b1[c+3], 0.f);
    uint2 p;
    p.x = h2_as_u(__float22half2_rn(make_float2(v0, v1)));
    p.y = h2_as_u(__float22half2_rn(make_float2(v2, v3)));
    *(uint2*)(g_hh + (size_t)node * 128 + c) = p;
}

// ---------------- propagate: g_ah[d] = dis[d] * sum_{s in N(d)} g_hh[s] ----------------
__global__ void k_prop() {
    int node = blockIdx.x * 8 + (threadIdx.x >> 5);
    if (node >= NN) return;
    int lane = threadIdx.x & 31;
    int beg = g_rowptr[node], end = g_rowptr[node + 1];
    float4 acc  = make_float4(0.f, 0.f, 0.f, 0.f);
    float4 acc2 = make_float4(0.f, 0.f, 0.f, 0.f);
    int j = beg;
    for (; j + 3 < end; j += 4) {
        int s0c = g_col[j],     s1c = g_col[j + 1];
        int s2c = g_col[j + 2], s3c = g_col[j + 3];
        uint2 h0 = *(const uint2*)(g_hh + (size_t)s0c * 128 + lane * 4);
        uint2 h1 = *(const uint2*)(g_hh + (size_t)s1c * 128 + lane * 4);
        uint2 h2 = *(const uint2*)(g_hh + (size_t)s2c * 128 + lane * 4);
        uint2 h3 = *(const uint2*)(g_hh + (size_t)s3c * 128 + lane * 4);
        float2 p0 = __half22float2(u_as_h2(h0.x)), p1 = __half22float2(u_as_h2(h0.y));
        float2 q0 = __half22float2(u_as_h2(h1.x)), q1 = __half22float2(u_as_h2(h1.y));
        float2 r0 = __half22float2(u_as_h2(h2.x)), r1 = __half22float2(u_as_h2(h2.y));
        float2 t0 = __half22float2(u_as_h2(h3.x)), t1 = __half22float2(u_as_h2(h3.y));
        acc.x  += p0.x; acc.y  += p0.y; acc.z  += p1.x; acc.w  += p1.y;
        acc2.x += q0.x; acc2.y += q0.y; acc2.z += q1.x; acc2.w += q1.y;
        acc.x  += r0.x; acc.y  += r0.y; acc.z  += r1.x; acc.w  += r1.y;
        acc2.x += t0.x; acc2.y += t0.y; acc2.z += t1.x; acc2.w += t1.y;
    }
    for (; j < end; j++) {
        uint2 h = *(const uint2*)(g_hh + (size_t)g_col[j] * 128 + lane * 4);
        float2 p0 = __half22float2(u_as_h2(h.x));
        float2 p1 = __half22float2(u_as_h2(h.y));
        acc.x += p0.x; acc.y += p0.y; acc.z += p1.x; acc.w += p1.y;
    }
    float dis = g_dis[node];
    acc.x = (acc.x + acc2.x) * dis; acc.y = (acc.y + acc2.y) * dis;
    acc.z = (acc.z + acc2.z) * dis; acc.w = (acc.w + acc2.w) * dis;
    uint2 o;
    o.x = h2_as_u(__float22half2_rn(make_float2(acc.x, acc.y)));
    o.y = h2_as_u(__float22half2_rn(make_float2(acc.z, acc.w)));
    *(uint2*)(g_ah + (size_t)node * 128 + lane * 4) = o;
}

// ---------------- GEMM (HMMA): g_hh = [dis*] relu(g_ah @ W + b) ----------------
#define PA 72    // A smem pitch (halfs)
#define PB 136   // B smem pitch (halfs)

__global__ __launch_bounds__(256, 2) void k_gemm(const float* __restrict__ W,
                                                 const float* __restrict__ bias,
                                                 int scale_out) {
    __shared__ __align__(16) __half As[128 * PA];  // 18KB
    __shared__ __align__(16) __half Bs[64 * PB];   // 17KB
    int t = threadIdx.x;
    int lane = t & 31, warp = t >> 5;
    int wm = warp & 3, wn = warp >> 2;             // 4 (m) x 2 (n) warps
    int row0 = blockIdx.x * 128;

    float acc[2][8][4];
    #pragma unroll
    for (int mt = 0; mt < 2; mt++)
        #pragma unroll
        for (int nt = 0; nt < 8; nt++)
            #pragma unroll
            for (int d = 0; d < 4; d++) acc[mt][nt][d] = 0.f;

    int lm = lane >> 3, lr = lane & 7;

    for (int k0 = 0; k0 < 128; k0 += 64) {
        #pragma unroll
        for (int i = 0; i < 4; i++) {
            int lin = t + i * 256;                 // 0..1023
            int r = lin >> 3, c8 = (lin & 7) * 8;
            uint4 v = make_uint4(0u, 0u, 0u, 0u);
            if (row0 + r < NN)
                v = *(const uint4*)(g_ah + (size_t)(row0 + r) * 128 + k0 + c8);
            *(uint4*)(As + r * PA + c8) = v;
        }
        #pragma unroll
        for (int i = 0; i < 8; i++) {
            int lin = t + i * 256;                 // 0..2047
            int kk = lin >> 5, c4 = (lin & 31) * 4;
            float4 wv = *(const float4*)(W + (size_t)(k0 + kk) * 128 + c4);
            uint2 p;
            p.x = h2_as_u(__float22half2_rn(make_float2(wv.x, wv.y)));
            p.y = h2_as_u(__float22half2_rn(make_float2(wv.z, wv.w)));
            *(uint2*)(Bs + kk * PB + c4) = p;
        }
        __syncthreads();

        #pragma unroll
        for (int kk = 0; kk < 64; kk += 16) {
            unsigned a[2][4];
            #pragma unroll
            for (int mt = 0; mt < 2; mt++) {
                const __half* ap = As + (wm * 32 + mt * 16 + (lm & 1) * 8 + lr) * PA
                                      + kk + (lm >> 1) * 8;
                unsigned addr = (unsigned)__cvta_generic_to_shared(ap);
                asm volatile("ldmatrix.sync.aligned.m8n8.x4.shared.b16 {%0,%1,%2,%3}, [%4];"
                             : "=r"(a[mt][0]), "=r"(a[mt][1]), "=r"(a[mt][2]), "=r"(a[mt][3])
                             : "r"(addr));
            }
            unsigned b[8][2];
            #pragma unroll
            for (int nt16 = 0; nt16 < 4; nt16++) {
                const __half* bp = Bs + (kk + (lm & 1) * 8 + lr) * PB
                                      + wn * 64 + nt16 * 16 + (lm >> 1) * 8;
                unsigned addr = (unsigned)__cvta_generic_to_shared(bp);
                asm volatile("ldmatrix.sync.aligned.m8n8.x4.trans.shared.b16 {%0,%1,%2,%3}, [%4];"
                             : "=r"(b[2*nt16][0]), "=r"(b[2*nt16][1]),
                               "=r"(b[2*nt16+1][0]), "=r"(b[2*nt16+1][1])
                             : "r"(addr));
            }
            #pragma unroll
            for (int mt = 0; mt < 2; mt++)
                #pragma unroll
                for (int nt = 0; nt < 8; nt++) {
                    asm volatile(
                        "mma.sync.aligned.m16n8k16.row.col.f32.f16.f16.f32 "
                        "{%0,%1,%2,%3}, {%4,%5,%6,%7}, {%8,%9}, {%0,%1,%2,%3};"
                        : "+f"(acc[mt][nt][0]), "+f"(acc[mt][nt][1]),
                          "+f"(acc[mt][nt][2]), "+f"(acc[mt][nt][3])
                        : "r"(a[mt][0]), "r"(a[mt][1]), "r"(a[mt][2]), "r"(a[mt][3]),
                          "r"(b[nt][0]), "r"(b[nt][1]));
                }
        }
        __syncthreads();
    }

    // epilogue: bias + relu (+ optional dis row-scale) -> fp16 h
    #pragma unroll
    for (int nt = 0; nt < 8; nt++) {
        int col = wn * 64 + nt * 8 + (lane & 3) * 2;
        float2 bv = *(const float2*)(bias + col);
        #pragma unroll
        for (int mt = 0; mt < 2; mt++) {
            int rA = row0 + wm * 32 + mt * 16 + (lane >> 2);
            if (rA < NN) {
                float sc = scale_out ? g_dis[rA] : 1.f;
                float2 v = make_float2(sc * fmaxf(acc[mt][nt][0] + bv.x, 0.f),
                                       sc * fmaxf(acc[mt][nt][1] + bv.y, 0.f));
                *(__half2*)(g_hh + (size_t)rA * 128 + col) = __float22half2_rn(v);
            }
            int rB = rA + 8;
            if (rB < NN) {
                float sc = scale_out ? g_dis[rB] : 1.f;
                float2 v = make_float2(sc * fmaxf(acc[mt][nt][2] + bv.x, 0.f),
                                       sc * fmaxf(acc[mt][nt][3] + bv.y, 0.f));
                *(__half2*)(g_hh + (size_t)rB * 128 + col) = __float22half2_rn(v);
            }
        }
    }
}

// ---------------- fused mean-pool + classifier head ----------------
__global__ void k_poolfinal(const int* __restrict__ batch, const float* __restrict__ Wl,
                            const float* __restrict__ bl, float* __restrict__ out) {
    __shared__ float spool[128];
    int g = blockIdx.x;   // 0..127
    int c = threadIdx.x;  // 0..127
    int lo = 0, hi = NN;
    while (lo < hi) { int m = (lo + hi) >> 1; if (batch[m] < g) lo = m + 1; else hi = m; }
    int st = lo;
    lo = st; hi = NN;
    while (lo < hi) { int m = (lo + hi) >> 1; if (batch[m] < g + 1) lo = m + 1; else hi = m; }
    int en = lo;
    float s0 = 0.f, s1 = 0.f, s2 = 0.f, s3 = 0.f;
    int n = st;
    for (; n + 3 < en; n += 4) {
        s0 += __half2float(g_hh[(size_t)(n + 0) * 128 + c]);
        s1 += __half2float(g_hh[(size_t)(n + 1) * 128 + c]);
        s2 += __half2float(g_hh[(size_t)(n + 2) * 128 + c]);
        s3 += __half2float(g_hh[(size_t)(n + 3) * 128 + c]);
    }
    for (; n < en; n++) s0 += __half2float(g_hh[(size_t)n * 128 + c]);
    float s = (s0 + s1) + (s2 + s3);
    int cnt = en - st;
    spool[c] = s / (float)(cnt > 0 ? cnt : 1);
    __syncthreads();

    int lane = c & 31, warp = c >> 5;              // 4 warps
    for (int j = warp; j < NC; j += 4) {
        float p = 0.f;
        #pragma unroll
        for (int i = 0; i < 4; i++) {
            int k = lane + 32 * i;
            p += spool[k] * Wl[k * NC + j];
        }
        #pragma unroll
        for (int o = 16; o; o >>= 1) p += __shfl_down_sync(0xffffffffu, p, o);
        if (lane == 0) out[g * NC + j] = p + bl[j];
    }
}

extern "C" void kernel_launch(void* const* d_in, const int* in_sizes, int n_in,
                              void* d_out, int out_size) {
    const float* x     = (const float*)d_in[0];
    const int*   ei    = (const int*)d_in[1];
    const int*   batch = (const int*)d_in[2];
    const float* W1    = (const float*)d_in[3];
    const float* b1    = (const float*)d_in[4];
    const float* W2    = (const float*)d_in[5];
    const float* b2    = (const float*)d_in[6];
    const float* W3    = (const float*)d_in[7];
    const float* b3    = (const float*)d_in[8];
    const float* Wl    = (const float*)d_in[9];
    const float* bl    = (const float*)d_in[10];
    float* out = (float*)d_out;

    const int* src = ei;          // edge_index[0]
    const int* dst = ei + NE;     // edge_index[1]

    // graph norm + CSR build (single-pass lookback scan; xs4 = dis*x precomputed)
    k_init <<<(NN + 255) / 256, 256>>>();
    k_deg  <<<(NE + 255) / 256, 256>>>(dst);
    k_scan1<<<NBLK, 256>>>(x);
    k_fill <<<(NT + 255) / 256, 256>>>(src, dst);

    // layer 1 -> g_hh (stores dis-scaled activations)
    k_layer1<<<(NN + 7) / 8, 256>>>(W1, b1);

    // layer 2 (epilogue stores dis-scaled)
    k_prop<<<(NN + 7) / 8, 256>>>();
    k_gemm<<<(NN + 127) / 128, 256>>>(W2, b2, 1);

    // layer 3 (plain activations for pooling)
    k_prop<<<(NN + 7) / 8, 256>>>();
    k_gemm<<<(NN + 127) / 128, 256>>>(W3, b3, 0);

    // pool + classifier head (fused)
    k_poolfinal<<<NG, HID>>>(batch, Wl, bl, out);
}